// round 9
// baseline (speedup 1.0000x reference)
#include <cuda_runtime.h>
#include <math.h>

#define NB      1024
#define LSCALE  128.0f
#define KPRE    300
#define KOUT    10
#define CAP     768
#define SEL     512
#define NW      16            // warps per CTA
#define WSEG    256           // cache entries per warp
#define RAW_T0  420
#define PPI     12
#define NPARTS  192
#define FULLM   0xFFFFFFFFu

// global scratch (static device globals: no allocation)
__device__ float  g_sc[NPARTS*CAP];
__device__ int    g_ix[NPARTS*CAP];
__device__ float4 g_bx[NPARTS*CAP];
__device__ int    g_cnt[NPARTS];
__device__ int    g_arrive[64];       // zero-init; merge CTA resets to 0

struct Ptrs {
    const float* cls[4];
    const float* box[4];
    const float* anc[4];
};

// 192 part-CTAs select per-part exact top-300-valid (logit domain) into
// global scratch; last CTA per (batch,level) group merges + NMS. All hot
// loops are atomic-free (warp-private compaction / warp-aggregated counters).
__global__ __launch_bounds__(512) void detect_kernel(Ptrs P, float* out, int out_size) {
    const int pid = blockIdx.x;
    const int b  = pid / PPI;
    const int pp = pid % PPI;
    int lvl, partIdx;
    if      (pp < 8)   { lvl = 0; partIdx = pp; }
    else if (pp < 10)  { lvl = 1; partIdx = pp - 8; }
    else if (pp == 10) { lvl = 2; partIdx = 0; }
    else               { lvl = 3; partIdx = 0; }
    const int HW    = 16384 >> (2*lvl);
    const int N     = 9 * HW;
    const int PARTN = (lvl==0) ? N/8 : (lvl==1) ? N/2 : N;   // 18432,18432,9216,2304
    const int j0    = partIdx * PARTN;
    const int flBK  = (lvl<=1) ? 128 : (lvl==2) ? 64 : 0;
    const float floorVal = (float)flBK * (1.0f/128.0f);
    const float* cls  = P.cls[lvl] + (size_t)b * N + j0;
    const float* boxp = P.box[lvl];
    const float* anc  = P.anc[lvl];
    const int tid = threadIdx.x, wid = tid >> 5, lane = tid & 31;
    const unsigned laneLT = (1u << lane) - 1u;

    __shared__ int hist[NB];
    __shared__ union {
        struct { float cval[NW*WSEG]; int cidx[NW*WSEG]; } sel;        // 32KB
        struct {
            unsigned long long key[SEL];
            float x1[KPRE], y1[KPRE], x2[KPRE], y2[KPRE], area[KPRE], logit[KPRE];
        } mrg;
    } U;
    __shared__ int wtot[16];
    __shared__ int s_seg[NW];
    __shared__ int s_cnt, s_cut, s_scnt, s_next, s_nk, s_last;
    __shared__ unsigned keepw[10];
    __shared__ int s_pc[8];

    // ---------------- select: stream phase (atomic-free) ----------------
    for (int i = tid; i < NB; i += 512) hist[i] = 0;
    if (tid == 0) s_cnt = 0;
    __syncthreads();

    const int n4 = PARTN >> 2;
    const float4* cls4 = (const float4*)cls;

    auto above_floor = [&](float x) -> bool {
        return (flBK == 0) ? (x > 0.0f) : (x >= floorVal);
    };

    int wbase = 0;   // per-warp cache fill count (uniform across warp)
    {
        const int rounds = (n4 + 511) >> 9;
        for (int r0 = 0; r0 < rounds; r0 += 8) {
            float4 v[8]; int idx[8];
            const int nb = (rounds - r0 < 8) ? (rounds - r0) : 8;
            #pragma unroll
            for (int k = 0; k < 8; k++) {
                int i = (r0 + k) * 512 + tid;
                idx[k] = i;
                v[k] = (k < nb && i < n4) ? cls4[i]
                       : make_float4(-1e9f, -1e9f, -1e9f, -1e9f);
            }
            #pragma unroll
            for (int k = 0; k < 8; k++) {
                if (k < nb) {
                    float xs[4] = {v[k].x, v[k].y, v[k].z, v[k].w};
                    #pragma unroll
                    for (int c = 0; c < 4; c++) {
                        float x = xs[c];
                        bool pr = above_floor(x);
                        unsigned mk = __ballot_sync(FULLM, pr);
                        if (mk) {
                            int off = wbase + __popc(mk & laneLT);
                            if (pr && off < WSEG) {
                                U.sel.cval[wid*WSEG + off] = x;
                                U.sel.cidx[wid*WSEG + off] = idx[k]*4 + c;
                            }
                            wbase += __popc(mk);
                        }
                    }
                }
            }
        }
    }
    if (lane == 0) s_seg[wid] = wbase;
    __syncthreads();

    bool cacheOK = true;
    #pragma unroll
    for (int s = 0; s < NW; s++) cacheOK = cacheOK && (s_seg[s] <= WSEG);

    // histogram of above-floor entries (from cache, or global rescan on overflow)
    if (cacheOK) {
        for (int t = tid; t < NW*WSEG; t += 512) {
            int w2 = t >> 8, o = t & (WSEG-1);
            if (o < s_seg[w2]) {
                float x = U.sel.cval[t];
                int bk = (int)(x * LSCALE); bk = bk > NB-1 ? NB-1 : bk;
                atomicAdd(&hist[bk], 1);
            }
        }
    } else {
        for (int i = tid; i < n4; i += 512) {
            float4 v = cls4[i];
            float xs[4] = {v.x, v.y, v.z, v.w};
            for (int c = 0; c < 4; c++) {
                float x = xs[c];
                if (above_floor(x)) {
                    int bk = (int)(x * LSCALE); bk = bk > NB-1 ? NB-1 : bk;
                    atomicAdd(&hist[bk], 1);
                }
            }
        }
    }

    // suffix count strictly after this thread's bucket pair [2t,2t+1]
    auto computeAbove = [&]() -> int {
        __syncthreads();
        int h = hist[2*tid] + hist[2*tid+1];
        int v = h;
        #pragma unroll
        for (int off = 1; off < 32; off <<= 1) {
            int t2 = __shfl_down_sync(FULLM, v, off);
            if (lane + off < 32) v += t2;
        }
        if (lane == 0) wtot[wid] = v;
        __syncthreads();
        int tail = 0;
        for (int w = wid + 1; w < 16; w++) tail += wtot[w];
        return (v - h) + tail;
    };

    // decode: returns validity, fills box
    auto decode = [&](float x, int j, float4& bx) -> bool {
        int a = j / HW;
        int rem = j - a*HW;
        const float* bp = boxp + ((size_t)(b*9 + a) * 4) * HW + rem;
        float d0 = bp[0], d1 = bp[HW], d2 = bp[2*HW], d3 = bp[3*HW];
        float4 an = ((const float4*)anc)[j];
        float w = an.z - an.x, h = an.w - an.y;
        float cx = an.x + 0.5f*w, cy = an.y + 0.5f*h;
        d0 = fminf(fmaxf(d0, -2.0f), 2.0f);
        d1 = fminf(fmaxf(d1, -2.0f), 2.0f);
        d2 = fminf(fmaxf(d2, -2.0f), 2.0f);
        d3 = fminf(fmaxf(d3, -2.0f), 2.0f);
        float px = cx + d0*w, py = cy + d1*h;
        float pw = w * expf(d2), ph = h * expf(d3);
        float x1 = fminf(fmaxf(px - 0.5f*pw, 0.0f), 1024.0f);
        float y1 = fminf(fmaxf(py - 0.5f*ph, 0.0f), 1024.0f);
        float x2 = fminf(fmaxf(px + 0.5f*pw, 0.0f), 1024.0f);
        float y2 = fminf(fmaxf(py + 0.5f*ph, 0.0f), 1024.0f);
        bx = make_float4(x1, y1, x2, y2);
        float bw = x2 - x1, bh = y2 - y1;
        return (bw > 1.0f && bh > 1.0f && bw < 2000.0f && bh < 2000.0f);
    };
    // warp-aggregated store of a valid candidate (call from converged point)
    auto agg_store = [&](bool valid, float x, int j, float4 bx) {
        unsigned mk = __ballot_sync(FULLM, valid);
        if (mk) {
            int ldr = __ffs(mk) - 1;
            int posB = 0;
            if (lane == ldr) posB = atomicAdd(&s_cnt, __popc(mk));
            posB = __shfl_sync(FULLM, posB, ldr);
            int pos = posB + __popc(mk & laneLT);
            if (valid && pos < CAP) {
                g_sc[pid*CAP + pos] = x;
                g_ix[pid*CAP + pos] = j;
                g_bx[pid*CAP + pos] = bx;
            }
        }
    };

    int above = computeAbove();
    bool histFull = (flBK == 0);
    int curCut = NB;
    int rawTarget = RAW_T0;
    while (true) {
        if (tid == 0) s_cut = 0;
        __syncthreads();
        {
            int cum1 = above + hist[2*tid+1];
            int cum0 = cum1 + hist[2*tid];
            int c = -1;
            if (2*tid+1 < curCut && cum1 >= rawTarget && above < rawTarget) c = 2*tid+1;
            if (2*tid   < curCut && cum0 >= rawTarget && cum1  < rawTarget) c = 2*tid;
            if (c >= 0) s_cut = c;     // unique crossing bucket
        }
        __syncthreads();
        int newCut = s_cut;

        if (!histFull && newCut < flBK) {
            for (int i = tid; i < n4; i += 512) {
                float4 v = cls4[i];
                float xs[4] = {v.x, v.y, v.z, v.w};
                for (int c = 0; c < 4; c++) {
                    float x = xs[c];
                    if (x > 0.0f && !above_floor(x)) {
                        int bk = (int)(x * LSCALE); bk = bk > NB-1 ? NB-1 : bk;
                        atomicAdd(&hist[bk], 1);
                    }
                }
            }
            histFull = true;
            above = computeAbove();
            continue;
        }

        if (cacheOK && newCut >= flBK) {
            // collect band from warp-private cache (uniform loop -> ballots safe)
            for (int t = tid; t < NW*WSEG; t += 512) {
                int w2 = t >> 8, o = t & (WSEG-1);
                bool have = (o < s_seg[w2]);
                float x = have ? U.sel.cval[t] : -1e9f;
                int bk = (int)(x * LSCALE); bk = bk > NB-1 ? NB-1 : bk;
                bool inband = have && bk >= newCut && bk < curCut;
                float4 bx; bool valid = false; int j = 0;
                if (inband) {
                    j = j0 + U.sel.cidx[t];
                    valid = decode(x, j, bx);
                }
                agg_store(valid, x, j, bx);
            }
        } else {
            // exact fallback: rescan global (uniform rounds -> ballots safe)
            const int rounds = (n4 + 511) >> 9;
            for (int r = 0; r < rounds; r++) {
                int i = r*512 + tid;
                float4 v = (i < n4) ? cls4[i] : make_float4(-1e9f,-1e9f,-1e9f,-1e9f);
                float xs[4] = {v.x, v.y, v.z, v.w};
                #pragma unroll
                for (int c = 0; c < 4; c++) {
                    float x = xs[c];
                    int bk = (int)(x * LSCALE); bk = bk > NB-1 ? NB-1 : bk;
                    bool inband = (x > 0.0f) && bk >= newCut && bk < curCut;
                    float4 bx; bool valid = false; int j = 0;
                    if (inband) {
                        j = j0 + i*4 + c;
                        valid = decode(x, j, bx);
                    }
                    agg_store(valid, x, j, bx);
                }
            }
        }
        __syncthreads();
        int cnt = s_cnt;
        curCut = newCut;
        if (cnt >= KPRE || curCut == 0) break;
        rawTarget += (KPRE - cnt) + 32;
        __syncthreads();
    }
    if (tid == 0) g_cnt[pid] = (s_cnt < CAP) ? s_cnt : CAP;

    // ---------------- arrival: last CTA in group merges ----------------
    __threadfence();
    __syncthreads();
    const int grpOffA[4] = {0, 8, 10, 11};
    const int npA[4]     = {8, 2, 1, 1};
    const int grp = b*4 + lvl;
    const int np  = npA[lvl];
    if (tid == 0) {
        int old = atomicAdd(&g_arrive[grp], 1);
        s_last = (old == np - 1);
        if (s_last) atomicExch(&g_arrive[grp], 0);
    }
    __syncthreads();
    if (!s_last) return;
    __threadfence();

    // ---------------- merge phase (one CTA per image-level) ----------------
    const int p0 = b*PPI + grpOffA[lvl];
    const bool vF = (out_size >= 3840);
    unsigned char* vB = (unsigned char*)out + 12800;
    const int slot0 = b*40 + lvl*10;
    {
        int base5 = b*200 + lvl*50;
        if (tid < 50) out[base5 + tid] = 0.0f;
        if (tid >= 64 && tid < 74) {
            int k = tid - 64;
            if (vF) out[3200 + slot0 + k] = 0.0f;
            else    vB[slot0 + k] = 0;
        }
    }
    for (int i = tid; i < NB; i += 512) hist[i] = 0;
    if (tid < np) s_pc[tid] = g_cnt[p0 + tid];
    if (tid == 0) { s_scnt = 0; s_cut = 0; s_nk = 0; }
    __syncthreads();

    // histogram over merged part entries (flattened uniform loop, L2-hot)
    const int tot = np * CAP;
    for (int t = tid; t < tot; t += 512) {
        int k = t / CAP, i = t - k*CAP;
        if (i < s_pc[k]) {
            float x = g_sc[(p0 + k)*CAP + i];
            int bk = (int)(x * LSCALE); bk = bk > NB-1 ? NB-1 : bk;
            atomicAdd(&hist[bk], 1);
        }
    }
    __syncthreads();
    {
        int h = hist[2*tid] + hist[2*tid+1];
        int v = h;
        #pragma unroll
        for (int off = 1; off < 32; off <<= 1) {
            int t2 = __shfl_down_sync(FULLM, v, off);
            if (lane + off < 32) v += t2;
        }
        if (lane == 0) wtot[wid] = v;
        __syncthreads();
        int tail = 0;
        for (int w = wid + 1; w < 16; w++) tail += wtot[w];
        int above2 = (v - h) + tail;
        int cum1 = above2 + hist[2*tid+1];
        int cum0 = cum1 + hist[2*tid];
        if (cum1 >= KPRE && above2 < KPRE) s_cut = 2*tid+1;
        if (cum0 >= KPRE && cum1  < KPRE) s_cut = 2*tid;
    }
    __syncthreads();
    int cut = s_cut;

    // collect superset of top-300 (warp-aggregated counter; uniform loop)
    {
        const int totR = (tot + 511) & ~511;
        for (int t = tid; t < totR; t += 512) {
            int k = (t < tot) ? t / CAP : 0;
            int i = (t < tot) ? t - k*CAP : CAP;
            bool have = (t < tot) && (i < s_pc[k]);
            float x = have ? g_sc[(p0 + k)*CAP + i] : -1e9f;
            int bk = (int)(x * LSCALE); bk = bk > NB-1 ? NB-1 : bk;
            bool pr = have && bk >= cut;
            unsigned mk = __ballot_sync(FULLM, pr);
            if (mk) {
                int ldr = __ffs(mk) - 1;
                int posB = 0;
                if (lane == ldr) posB = atomicAdd(&s_scnt, __popc(mk));
                posB = __shfl_sync(FULLM, posB, ldr);
                int pos = posB + __popc(mk & laneLT);
                if (pr && pos < SEL) {
                    unsigned j = (unsigned)g_ix[(p0 + k)*CAP + i];
                    int rel = k*CAP + i;
                    unsigned lo = ((262143u - j) << 13) | (unsigned)rel;
                    U.mrg.key[pos] = ((unsigned long long)__float_as_uint(x) << 32)
                                   | (unsigned long long)lo;
                }
            }
        }
    }
    __syncthreads();
    int scnt = s_scnt < SEL ? s_scnt : SEL;
    for (int i = scnt + tid; i < SEL; i += 512) U.mrg.key[i] = 0ull;
    __syncthreads();

    // bitonic sort descending, 512 elems / 512 threads
    {
        unsigned long long key = U.mrg.key[tid];
        __syncthreads();
        #pragma unroll
        for (int k = 2; k <= SEL; k <<= 1) {
            bool segDesc = ((tid & k) == 0);
            #pragma unroll
            for (int j = k >> 1; j > 0; j >>= 1) {
                unsigned long long okey;
                if (j >= 32) {
                    U.mrg.key[tid] = key;
                    __syncthreads();
                    okey = U.mrg.key[tid ^ j];
                    __syncthreads();
                } else {
                    unsigned hi = __shfl_xor_sync(FULLM, (unsigned)(key >> 32), j);
                    unsigned lo = __shfl_xor_sync(FULLM, (unsigned)key, j);
                    okey = ((unsigned long long)hi << 32) | lo;
                }
                bool keepMax = (((tid & j) == 0) == segDesc);
                bool take = keepMax ? (okey > key) : (okey < key);
                if (take) key = okey;
            }
        }
        U.mrg.key[tid] = key;
        __syncthreads();
    }

    const int m = scnt < KPRE ? scnt : KPRE;
    for (int i = tid; i < m; i += 512) {
        unsigned long long key = U.mrg.key[i];
        int rel = (int)(key & 0x1FFFu);
        float4 bb = g_bx[p0*CAP + rel];
        U.mrg.x1[i] = bb.x; U.mrg.y1[i] = bb.y;
        U.mrg.x2[i] = bb.z; U.mrg.y2[i] = bb.w;
        U.mrg.area[i] = (bb.z - bb.x) * (bb.w - bb.y);
        U.mrg.logit[i] = __uint_as_float((unsigned)(key >> 32));
    }
    if (tid < 10) {
        int lo = tid * 32;
        unsigned w;
        if (m >= lo + 32) w = 0xFFFFFFFFu;
        else if (m > lo)  w = (1u << (m - lo)) - 1u;
        else              w = 0u;
        keepw[tid] = w;
    }
    __syncthreads();

    // greedy NMS, one round per kept box (<=10); exact prefix argument
    for (int round = 0; round <= KOUT; round++) {
        if (tid < 32) {
            unsigned v = (tid < 10) ? keepw[tid] : 0u;
            unsigned nz = __ballot_sync(FULLM, v != 0u);
            int w = __ffs(nz) - 1;
            unsigned vw = __shfl_sync(FULLM, v, (w < 0) ? 0 : w);
            if (tid == 0) s_next = nz ? (w*32 + __ffs(vw) - 1) : -1;
        }
        __syncthreads();
        int i = s_next;
        if (i < 0 || s_nk >= KOUT) break;

        float bx1 = U.mrg.x1[i], by1 = U.mrg.y1[i];
        float bx2 = U.mrg.x2[i], by2 = U.mrg.y2[i];
        float ba  = U.mrg.area[i];

        if (tid == 0) {
            int nk = s_nk;
            float sc = 1.0f / (1.0f + expf(-U.mrg.logit[i]));
            int s5 = b*200 + (lvl*10 + nk)*5;
            out[s5+0] = bx1; out[s5+1] = by1;
            out[s5+2] = bx2; out[s5+3] = by2;
            out[s5+4] = sc;
            if (vF) out[3200 + slot0 + nk] = 1.0f;
            else    vB[slot0 + nk] = 1;
            s_nk = nk + 1;
            atomicAnd(&keepw[i >> 5], ~(1u << (i & 31)));
        }
        if (tid > i && tid < m && ((keepw[tid >> 5] >> (tid & 31)) & 1u)) {
            float ix1 = fmaxf(bx1, U.mrg.x1[tid]);
            float iy1 = fmaxf(by1, U.mrg.y1[tid]);
            float ix2 = fminf(bx2, U.mrg.x2[tid]);
            float iy2 = fminf(by2, U.mrg.y2[tid]);
            float iw = fmaxf(ix2 - ix1, 0.0f), ih = fmaxf(iy2 - iy1, 0.0f);
            float inter = iw * ih;
            float iou = inter / (ba + U.mrg.area[tid] - inter + 1e-9f);
            if (iou > 0.3f) atomicAnd(&keepw[tid >> 5], ~(1u << (tid & 31)));
        }
        __syncthreads();
    }
}

// ---------------------------------------------------------------------------
extern "C" void kernel_launch(void* const* d_in, const int* in_sizes, int n_in,
                              void* d_out, int out_size) {
    Ptrs P;
    if (n_in >= 2 && in_sizes[0] == 2359296 && in_sizes[1] == 9437184) {
        for (int l = 0; l < 4; l++) {
            P.cls[l] = (const float*)d_in[3*l + 0];
            P.box[l] = (const float*)d_in[3*l + 1];
            P.anc[l] = (const float*)d_in[3*l + 2];
        }
    } else if (n_in >= 1 && in_sizes[0] == 2359296) {
        for (int l = 0; l < 4; l++) {
            P.cls[l] = (const float*)d_in[l];
            P.box[l] = (const float*)d_in[4 + l];
            P.anc[l] = (const float*)d_in[8 + l];
        }
    } else {
        for (int l = 0; l < 4; l++) {
            P.anc[l] = (const float*)d_in[l];
            P.box[l] = (const float*)d_in[4 + l];
            P.cls[l] = (const float*)d_in[8 + l];
        }
    }
    detect_kernel<<<NPARTS, 512>>>(P, (float*)d_out, out_size);
}

// round 10
// speedup vs baseline: 1.5554x; 1.5554x over previous
#include <cuda_runtime.h>
#include <math.h>

#define NB       1024
#define LSCALE   128.0f
#define KPRE     300
#define KOUT     10
#define SORTN    512
#define CANDCAP  512
#define NW       32
#define WSEG     96
#define RAW_T0   340
#define FULLM    0xFFFFFFFFu

struct Ptrs {
    const float* cls[4];
    const float* box[4];
    const float* anc[4];
};

// One CTA per (batch,level). Stream cls with a high per-level floor filter
// into per-warp smem caches; histogram the small cache; exact top-K cut;
// decode band; 512-wide bitonic sort (key = score|~ancidx|slot preserves
// lax.top_k tie order); register NMS. Exactness guards: cache overflow ->
// global rescan; cut below floor -> cold histogram extension; candidate
// overflow -> band re-tighten.
__global__ __launch_bounds__(1024) void detect_kernel(Ptrs P, float* out, int out_size) {
    const int img = blockIdx.x;
    const int b   = img >> 2;
    const int lvl = img & 3;
    const int HW  = 16384 >> (2*lvl);
    const int N   = 9 * HW;
    const int flBK = (lvl==0) ? 336 : (lvl==1) ? 256 : (lvl==2) ? 160 : 64;
    const float floorVal = (float)flBK * (1.0f/128.0f);   // exact
    const float* cls  = P.cls[lvl] + (size_t)b * N;
    const float* boxp = P.box[lvl];
    const float* anc  = P.anc[lvl];
    const int tid = threadIdx.x, wid = tid >> 5, lane = tid & 31;

    __shared__ int   hist[NB];
    __shared__ float cval[NW*WSEG];
    __shared__ int   cidx[NW*WSEG];
    __shared__ unsigned long long sKey[SORTN];
    __shared__ float4 candBox[CANDCAP];
    __shared__ int   wtot[32];
    __shared__ int   s_seg[NW];
    __shared__ unsigned s_flags;
    __shared__ int   s_cnt, s_cut, s_next, s_nk;
    __shared__ unsigned keepw[10];

    const bool vF = (out_size >= 3840);
    unsigned char* vB = (unsigned char*)out + 12800;
    const int slot0 = b*40 + lvl*10;

    // zero this CTA's output region (d_out is poisoned)
    {
        int base5 = b*200 + lvl*50;
        if (tid < 50) out[base5 + tid] = 0.0f;
        if (tid >= 64 && tid < 74) {
            int k = tid - 64;
            if (vF) out[3200 + slot0 + k] = 0.0f;
            else    vB[slot0 + k] = 0;
        }
    }
    hist[tid] = 0;
    if (tid < NW) s_seg[tid] = 0;
    __syncthreads();

    const int n4 = N >> 2;
    const float4* cls4 = (const float4*)cls;
    const int segBase = wid * WSEG;

    // ---- stream: filter above floor into per-warp cache (no histogram) ----
    auto proc = [&](float4 v, int i4) {
        float mx = fmaxf(fmaxf(v.x, v.y), fmaxf(v.z, v.w));
        if (mx >= floorVal) {                 // rare
            float xs[4] = {v.x, v.y, v.z, v.w};
            #pragma unroll
            for (int c = 0; c < 4; c++) {
                float x = xs[c];
                if (x >= floorVal) {
                    int p = atomicAdd(&s_seg[wid], 1);
                    if (p < WSEG) { cval[segBase + p] = x; cidx[segBase + p] = i4*4 + c; }
                }
            }
        }
    };
    {
        int i = tid;
        for (; i + 7*1024 < n4; i += 8*1024) {
            float4 v0 = cls4[i];          float4 v1 = cls4[i + 1024];
            float4 v2 = cls4[i + 2048];   float4 v3 = cls4[i + 3072];
            float4 v4 = cls4[i + 4096];   float4 v5 = cls4[i + 5120];
            float4 v6 = cls4[i + 6144];   float4 v7 = cls4[i + 7168];
            proc(v0, i);        proc(v1, i + 1024);
            proc(v2, i + 2048); proc(v3, i + 3072);
            proc(v4, i + 4096); proc(v5, i + 5120);
            proc(v6, i + 6144); proc(v7, i + 7168);
        }
        for (; i < n4; i += 1024) proc(cls4[i], i);
    }
    __syncthreads();

    if (tid < 32) {
        unsigned bad = __ballot_sync(FULLM, s_seg[tid] > WSEG);
        if (tid == 0) s_flags = bad;
    }
    __syncthreads();
    const bool cacheOK = (s_flags == 0);

    // ---- histogram (from cache, or full global scan if cache overflowed) ----
    if (cacheOK) {
        for (int t = tid; t < NW*WSEG; t += 1024) {
            int w = t / WSEG, o = t - w*WSEG;
            if (o < s_seg[w]) {
                float x = cval[t];
                int bk = (int)(x * LSCALE); bk = bk > NB-1 ? NB-1 : bk;
                atomicAdd(&hist[bk], 1);
            }
        }
    } else {
        for (int i = tid; i < n4; i += 1024) {
            float4 v = cls4[i];
            float xs[4] = {v.x, v.y, v.z, v.w};
            for (int c = 0; c < 4; c++) {
                float x = xs[c];
                if (x > 0.0f) {
                    int bk = (int)(x * LSCALE); bk = bk > NB-1 ? NB-1 : bk;
                    atomicAdd(&hist[bk], 1);
                }
            }
        }
    }

    // suffix count strictly after this thread's single bucket (tid == bucket)
    auto computeAbove = [&]() -> int {
        __syncthreads();
        int h = hist[tid];
        int v = h;
        #pragma unroll
        for (int off = 1; off < 32; off <<= 1) {
            int t2 = __shfl_down_sync(FULLM, v, off);
            if (lane + off < 32) v += t2;
        }
        if (lane == 0) wtot[wid] = v;
        __syncthreads();
        int tail = 0;
        for (int w = wid + 1; w < 32; w++) tail += wtot[w];
        return (v - h) + tail;
    };

    auto decode_store = [&](float x, int j) {
        int a = j / HW;
        int rem = j - a*HW;
        const float* bp = boxp + ((size_t)(b*9 + a) * 4) * HW + rem;
        float d0 = bp[0], d1 = bp[HW], d2 = bp[2*HW], d3 = bp[3*HW];
        float4 an = ((const float4*)anc)[j];
        float w = an.z - an.x, h = an.w - an.y;
        float cx = an.x + 0.5f*w, cy = an.y + 0.5f*h;
        d0 = fminf(fmaxf(d0, -2.0f), 2.0f);
        d1 = fminf(fmaxf(d1, -2.0f), 2.0f);
        d2 = fminf(fmaxf(d2, -2.0f), 2.0f);
        d3 = fminf(fmaxf(d3, -2.0f), 2.0f);
        float px = cx + d0*w, py = cy + d1*h;
        float pw = w * expf(d2), ph = h * expf(d3);
        float x1 = fminf(fmaxf(px - 0.5f*pw, 0.0f), 1024.0f);
        float y1 = fminf(fmaxf(py - 0.5f*ph, 0.0f), 1024.0f);
        float x2 = fminf(fmaxf(px + 0.5f*pw, 0.0f), 1024.0f);
        float y2 = fminf(fmaxf(py + 0.5f*ph, 0.0f), 1024.0f);
        float bw = x2 - x1, bh = y2 - y1;
        if (bw > 1.0f && bh > 1.0f && bw < 2000.0f && bh < 2000.0f) {
            int pos = atomicAdd(&s_cnt, 1);
            if (pos < CANDCAP) {
                unsigned lo = ((262143u - (unsigned)j) << 13) | (unsigned)pos;
                sKey[pos] = ((unsigned long long)__float_as_uint(x) << 32) | lo;
                candBox[pos] = make_float4(x1, y1, x2, y2);
            }
        }
    };

    // ---- exact band selection loop (usually a single iteration) ----
    bool histFull = !cacheOK;       // global path built the full histogram
    int rawTarget = RAW_T0;
    int guard = 0;
    int cnt = 0, cut = 0;
    while (true) {
        if (tid == 0) s_cut = 0;
        int above = computeAbove();
        {
            int cum = above + hist[tid];
            if (cum >= rawTarget && above < rawTarget) s_cut = tid;
        }
        __syncthreads();
        cut = s_cut;

        if (!histFull && cut < flBK) {
            // cold: extend histogram below the floor (exactness guard)
            for (int i = tid; i < n4; i += 1024) {
                float4 v = cls4[i];
                float xs[4] = {v.x, v.y, v.z, v.w};
                for (int c = 0; c < 4; c++) {
                    float x = xs[c];
                    if (x > 0.0f && x < floorVal) {
                        int bk = (int)(x * LSCALE); bk = bk > NB-1 ? NB-1 : bk;
                        atomicAdd(&hist[bk], 1);
                    }
                }
            }
            histFull = true;
            continue;
        }

        if (tid == 0) s_cnt = 0;
        __syncthreads();
        const float cutVal = (float)cut * (1.0f/128.0f);   // exact

        if (cacheOK && cut >= flBK) {
            for (int t = tid; t < NW*WSEG; t += 1024) {
                int w = t / WSEG, o = t - w*WSEG;
                if (o < s_seg[w]) {
                    float x = cval[t];
                    if (x >= cutVal) decode_store(x, cidx[t]);
                }
            }
        } else {
            for (int i = tid; i < n4; i += 1024) {
                float4 v = cls4[i];
                float xs[4] = {v.x, v.y, v.z, v.w};
                for (int c = 0; c < 4; c++) {
                    float x = xs[c];
                    if (x > 0.0f && x >= cutVal) decode_store(x, i*4 + c);
                }
            }
        }
        __syncthreads();
        cnt = s_cnt;
        if (++guard > 8) break;
        if (cnt > CANDCAP) {
            if (rawTarget > KPRE) { rawTarget = KPRE; continue; }  // tighten band
            break;
        }
        if (cnt >= KPRE || cut == 0) break;
        rawTarget += (KPRE - cnt) + 32;    // valid shortfall -> widen band
    }

    int scnt = cnt < CANDCAP ? cnt : CANDCAP;
    if (tid >= scnt && tid < SORTN) sKey[tid] = 0ull;
    __syncthreads();

    // ---- bitonic sort descending, 512 elems (threads >=512 idle at bars) ----
    {
        unsigned long long key = (tid < SORTN) ? sKey[tid] : 0ull;
        __syncthreads();
        #pragma unroll
        for (int k = 2; k <= SORTN; k <<= 1) {
            bool segDesc = ((tid & k) == 0);
            #pragma unroll
            for (int j = k >> 1; j > 0; j >>= 1) {
                unsigned long long okey;
                if (j >= 32) {
                    if (tid < SORTN) sKey[tid] = key;
                    __syncthreads();
                    okey = (tid < SORTN) ? sKey[tid ^ j] : 0ull;
                    __syncthreads();
                } else {
                    unsigned hi = __shfl_xor_sync(FULLM, (unsigned)(key >> 32), j);
                    unsigned lo = __shfl_xor_sync(FULLM, (unsigned)key, j);
                    okey = ((unsigned long long)hi << 32) | lo;
                }
                bool keepMax = (((tid & j) == 0) == segDesc);
                bool take = keepMax ? (okey > key) : (okey < key);
                if (tid < SORTN && take) key = okey;
            }
        }
        if (tid < SORTN) sKey[tid] = key;
        __syncthreads();
    }

    // ---- NMS: each thread holds its candidate's box in registers ----
    const int m = scnt < KPRE ? scnt : KPRE;
    float mx1 = 0, my1 = 0, mx2 = 0, my2 = 0, mar = 0;
    if (tid < m) {
        unsigned long long kk = sKey[tid];
        float4 bb = candBox[(int)(kk & 0x1FFFu)];
        mx1 = bb.x; my1 = bb.y; mx2 = bb.z; my2 = bb.w;
        mar = (bb.z - bb.x) * (bb.w - bb.y);
    }
    if (tid < 10) {
        int lo = tid * 32;
        unsigned w;
        if (m >= lo + 32) w = FULLM;
        else if (m > lo)  w = (1u << (m - lo)) - 1u;
        else              w = 0u;
        keepw[tid] = w;
    }
    if (tid == 0) s_nk = 0;
    __syncthreads();

    for (int round = 0; round <= KOUT; round++) {
        if (tid < 32) {
            unsigned v = (tid < 10) ? keepw[tid] : 0u;
            unsigned nz = __ballot_sync(FULLM, v != 0u);
            int w = __ffs(nz) - 1;
            unsigned vw = __shfl_sync(FULLM, v, (w < 0) ? 0 : w);
            if (tid == 0) s_next = nz ? (w*32 + __ffs(vw) - 1) : -1;
        }
        __syncthreads();
        int i = s_next;
        if (i < 0 || s_nk >= KOUT) break;

        unsigned long long ki = sKey[i];               // broadcast
        float4 bi = candBox[(int)(ki & 0x1FFFu)];      // broadcast
        float ba = (bi.z - bi.x) * (bi.w - bi.y);

        if (tid == 0) {
            int nk = s_nk;
            float logit = __uint_as_float((unsigned)(ki >> 32));
            float sc = 1.0f / (1.0f + expf(-logit));
            int s5 = b*200 + (lvl*10 + nk)*5;
            out[s5+0] = bi.x; out[s5+1] = bi.y;
            out[s5+2] = bi.z; out[s5+3] = bi.w;
            out[s5+4] = sc;
            if (vF) out[3200 + slot0 + nk] = 1.0f;
            else    vB[slot0 + nk] = 1;
            s_nk = nk + 1;
            atomicAnd(&keepw[i >> 5], ~(1u << (i & 31)));
        }
        if (tid > i && tid < m && ((keepw[tid >> 5] >> (tid & 31)) & 1u)) {
            float ix1 = fmaxf(bi.x, mx1), iy1 = fmaxf(bi.y, my1);
            float ix2 = fminf(bi.z, mx2), iy2 = fminf(bi.w, my2);
            float iw = fmaxf(ix2 - ix1, 0.0f), ih = fmaxf(iy2 - iy1, 0.0f);
            float inter = iw * ih;
            float iou = inter / (ba + mar - inter + 1e-9f);
            if (iou > 0.3f) atomicAnd(&keepw[tid >> 5], ~(1u << (tid & 31)));
        }
        __syncthreads();
    }
}

// ---------------------------------------------------------------------------
extern "C" void kernel_launch(void* const* d_in, const int* in_sizes, int n_in,
                              void* d_out, int out_size) {
    Ptrs P;
    if (n_in >= 2 && in_sizes[0] == 2359296 && in_sizes[1] == 9437184) {
        for (int l = 0; l < 4; l++) {
            P.cls[l] = (const float*)d_in[3*l + 0];
            P.box[l] = (const float*)d_in[3*l + 1];
            P.anc[l] = (const float*)d_in[3*l + 2];
        }
    } else if (n_in >= 1 && in_sizes[0] == 2359296) {
        for (int l = 0; l < 4; l++) {
            P.cls[l] = (const float*)d_in[l];
            P.box[l] = (const float*)d_in[4 + l];
            P.anc[l] = (const float*)d_in[8 + l];
        }
    } else {
        for (int l = 0; l < 4; l++) {
            P.anc[l] = (const float*)d_in[l];
            P.box[l] = (const float*)d_in[4 + l];
            P.cls[l] = (const float*)d_in[8 + l];
        }
    }
    detect_kernel<<<64, 1024>>>(P, (float*)d_out, out_size);
}